// round 1
// baseline (speedup 1.0000x reference)
#include <cuda_runtime.h>
#include <math.h>

#define N_NODES 512
#define DIM 128
#define NA 192          // total anchors
#define G3 384          // 3*DIM

// ---------------- scratch (no allocations allowed) ----------------
__device__ float g_x[N_NODES * DIM];        // positional-encoded embeddings
__device__ float g_abn[N_NODES];            // smoothed abnormal score
__device__ float g_tpos[N_NODES];           // time position * audio_len
__device__ float g_Gi[6 * N_NODES * G3];    // precomputed input gates per (scale,dir)
__device__ float g_hout[NA * 2 * DIM];      // final hidden per (anchor,dir)
__device__ float g_abnout[NA * 2];          // final abn hidden per (anchor,dir)

__device__ __forceinline__ float sigf(float x) { return 1.f / (1.f + __expf(-x)); }
__device__ __forceinline__ float tanhfast(float x) { return 2.f / (1.f + __expf(-2.f * x)) - 1.f; }

// ---------------- kernel 1: preprocess ----------------
// x = emb + 0.05*sin(tp*freq); abnormal = softmax(conv5(node_pred))[:,0]; tpos = tp*al
__global__ void k_pre(const float* __restrict__ emb, const float* __restrict__ tp,
                      const float* __restrict__ pred, const float* __restrict__ al_p,
                      const float* __restrict__ kern)
{
    int tid = blockIdx.x * blockDim.x + threadIdx.x;
    if (tid < N_NODES * DIM) {
        int n = tid >> 7, d = tid & 127;
        float freq = (10.f / 127.f) * (float)d;
        g_x[tid] = emb[tid] + 0.05f * sinf(tp[n] * freq);
    }
    if (tid < N_NODES) {
        int n = tid;
        float kv[5];
        #pragma unroll
        for (int k = 0; k < 5; k++) kv[k] = kern[k];
        float sv[5];
        #pragma unroll
        for (int c = 0; c < 5; c++) {
            float acc = 0.f;
            #pragma unroll
            for (int k = 0; k < 5; k++) {
                int nn = n + k - 2;
                if (nn >= 0 && nn < N_NODES) acc += kv[k] * pred[nn * 5 + c];
            }
            sv[c] = acc;
        }
        float m = sv[0];
        #pragma unroll
        for (int c = 1; c < 5; c++) m = fmaxf(m, sv[c]);
        float den = 0.f;
        #pragma unroll
        for (int c = 0; c < 5; c++) den += __expf(sv[c] - m);
        g_abn[n] = __expf(sv[0] - m) / den;
        g_tpos[n] = tp[n] * al_p[0];
    }
}

// ---------------- kernel 2: Gi = x @ Wih^T + bih for 6 (scale,dir) sets ----------------
// grid: (32 node-tiles of 16, 6 sd), 384 threads = one output gate row each
__global__ __launch_bounds__(384) void k_gi(const float* __restrict__ Wih,
                                            const float* __restrict__ bih)
{
    int sd = blockIdx.y;
    int tile = blockIdx.x;      // 16 nodes per tile
    __shared__ __align__(16) float sxT[DIM][16];   // transposed x tile
    int t = threadIdx.x;
    for (int i = t; i < 16 * DIM; i += 384) {
        int nn = i >> 7, k = i & 127;
        sxT[k][nn] = g_x[(tile * 16 + nn) * DIM + k];
    }
    __syncthreads();

    const float* w = Wih + ((size_t)sd * G3 + t) * DIM;
    float b = bih[sd * G3 + t];
    float acc[16];
    #pragma unroll
    for (int nn = 0; nn < 16; nn++) acc[nn] = b;
    for (int k = 0; k < DIM; k++) {
        float wk = w[k];
        const float4* row = (const float4*)sxT[k];
        float4 a0 = row[0], a1 = row[1], a2 = row[2], a3 = row[3];
        acc[0]  += wk * a0.x; acc[1]  += wk * a0.y; acc[2]  += wk * a0.z; acc[3]  += wk * a0.w;
        acc[4]  += wk * a1.x; acc[5]  += wk * a1.y; acc[6]  += wk * a1.z; acc[7]  += wk * a1.w;
        acc[8]  += wk * a2.x; acc[9]  += wk * a2.y; acc[10] += wk * a2.z; acc[11] += wk * a2.w;
        acc[12] += wk * a3.x; acc[13] += wk * a3.y; acc[14] += wk * a3.z; acc[15] += wk * a3.w;
    }
    #pragma unroll
    for (int nn = 0; nn < 16; nn++)
        g_Gi[((size_t)sd * N_NODES + (tile * 16 + nn)) * G3 + t] = acc[nn];
}

// ---------------- kernel 3: per-(anchor,dir) GRU recurrence ----------------
// 384 threads: thread j owns Whh row j in registers. h broadcast from SMEM.
__global__ __launch_bounds__(384, 1) void k_gru(const float* __restrict__ anchors,
                                                const float* __restrict__ Whh,
                                                const float* __restrict__ bhh,
                                                const float* __restrict__ aWih,
                                                const float* __restrict__ aWhh,
                                                const float* __restrict__ abih,
                                                const float* __restrict__ abhh)
{
    int a = blockIdx.x;          // 0..191
    int dir = blockIdx.y;        // 0 fwd, 1 bwd
    int s = a >> 6;              // 64 anchors per scale
    int sd = s * 2 + dir;
    int t = threadIdx.x;

    __shared__ __align__(16) float sh_h[DIM];
    __shared__ float sh_gh[G3];
    __shared__ unsigned short sh_idx[N_NODES];
    __shared__ int sh_len;
    __shared__ float sh_abn_h;

    float stt = anchors[a * 2], enn = anchors[a * 2 + 1];

    // compact selected nodes (original-order) with warp 0
    if (t < 32) {
        int off = 0;
        for (int base = 0; base < N_NODES; base += 32) {
            int n = base + t;
            float tp = g_tpos[n];
            bool m = (tp >= stt) && (tp <= enn);
            unsigned bal = __ballot_sync(0xffffffffu, m);
            if (m) sh_idx[off + __popc(bal & ((1u << t) - 1u))] = (unsigned short)n;
            off += __popc(bal);
        }
        if (t == 0) { sh_len = off; sh_abn_h = 0.f; }
    }
    if (t < DIM) sh_h[t] = 0.f;

    // recurrent weights into registers
    const float4* wrow = (const float4*)(Whh + ((size_t)sd * G3 + t) * DIM);
    float4 w4[32];
    #pragma unroll
    for (int i = 0; i < 32; i++) w4[i] = wrow[i];
    float bh = bhh[sd * G3 + t];

    // abn GRU weights (scalar cell) for thread 128
    float awi0 = 0, awi1 = 0, awi2 = 0, awh0 = 0, awh1 = 0, awh2 = 0;
    float abi0 = 0, abi1 = 0, abi2 = 0, abh0 = 0, abh1 = 0, abh2 = 0;
    if (t == 128) {
        int base = sd * 3;
        awi0 = aWih[base]; awi1 = aWih[base + 1]; awi2 = aWih[base + 2];
        awh0 = aWhh[base]; awh1 = aWhh[base + 1]; awh2 = aWhh[base + 2];
        abi0 = abih[base]; abi1 = abih[base + 1]; abi2 = abih[base + 2];
        abh0 = abhh[base]; abh1 = abhh[base + 1]; abh2 = abhh[base + 2];
    }
    __syncthreads();

    int len = sh_len;
    const float* Gi = g_Gi + (size_t)sd * N_NODES * G3;

    for (int step = 0; step < len; step++) {
        int node = dir ? (int)sh_idx[len - 1 - step] : (int)sh_idx[step];
        float gi_r = 0, gi_z = 0, gi_n = 0, ab_in = 0;
        if (t < DIM) {                    // issue gate-input loads early (latency hide)
            const float* gp = Gi + (size_t)node * G3;
            gi_r = gp[t]; gi_z = gp[DIM + t]; gi_n = gp[2 * DIM + t];
        } else if (t == 128) {
            ab_in = g_abn[node];
        }

        // gh[j] = Whh[j]·h + bhh[j]
        float acc = bh;
        const float4* h4 = (const float4*)sh_h;
        #pragma unroll
        for (int i = 0; i < 32; i++) {
            float4 hv = h4[i];
            float4 wv = w4[i];
            acc += wv.x * hv.x; acc += wv.y * hv.y;
            acc += wv.z * hv.z; acc += wv.w * hv.w;
        }
        sh_gh[t] = acc;
        __syncthreads();

        if (t < DIM) {
            float r  = sigf(gi_r + sh_gh[t]);
            float z  = sigf(gi_z + sh_gh[DIM + t]);
            float nn = tanhfast(gi_n + r * sh_gh[2 * DIM + t]);
            sh_h[t] = (1.f - z) * nn + z * sh_h[t];
        } else if (t == 128) {
            float h = sh_abn_h;
            float r  = sigf(awi0 * ab_in + abi0 + awh0 * h + abh0);
            float z  = sigf(awi1 * ab_in + abi1 + awh1 * h + abh1);
            float nn = tanhfast(awi2 * ab_in + abi2 + r * (awh2 * h + abh2));
            sh_abn_h = (1.f - z) * nn + z * h;
        }
        __syncthreads();
    }

    if (t < DIM) g_hout[((size_t)a * 2 + dir) * DIM + t] = sh_h[t];
    if (t == 128) g_abnout[a * 2 + dir] = sh_abn_h;
}

// ---------------- kernel 4: per-anchor MLP head + distribution decode ----------------
__global__ __launch_bounds__(256) void k_head(const float* __restrict__ anchors,
                                              const float* __restrict__ al_p,
                                              const float* __restrict__ W1, const float* __restrict__ b1,
                                              const float* __restrict__ W2, const float* __restrict__ b2,
                                              const float* __restrict__ W3, const float* __restrict__ b3,
                                              const float* __restrict__ start_w,
                                              const float* __restrict__ end_w,
                                              float* __restrict__ out)
{
    int a = blockIdx.x;
    int s = a >> 6;
    int t = threadIdx.x;
    const int FIN = 2 * DIM + 3;   // 259
    const int FOUT = 47;           // 2*21 + 1 + 4

    __shared__ float sf[FIN + 1];
    __shared__ float h1[256];
    __shared__ float h2[256];
    __shared__ float o[FOUT];

    float al = al_p[0];
    if (t < DIM) {
        sf[t]       = g_hout[((size_t)a * 2 + 0) * DIM + t];
        sf[DIM + t] = g_hout[((size_t)a * 2 + 1) * DIM + t];
    }
    if (t == 0) {
        sf[256] = 0.5f * (g_abnout[a * 2] + g_abnout[a * 2 + 1]);
        float stt = anchors[a * 2], enn = anchors[a * 2 + 1];
        sf[257] = (stt + enn) * 0.5f / al;
        sf[258] = (enn - stt) / al;
    }
    __syncthreads();

    const float* W1s = W1 + (size_t)s * FIN * 256;
    float acc = b1[s * 256 + t];
    for (int i = 0; i < FIN; i++) acc += W1s[i * 256 + t] * sf[i];
    h1[t] = fmaxf(acc, 0.f);
    __syncthreads();

    const float* W2s = W2 + (size_t)s * 256 * 256;
    acc = b2[s * 256 + t];
    for (int i = 0; i < 256; i++) acc += W2s[i * 256 + t] * h1[i];
    h2[t] = fmaxf(acc, 0.f);
    __syncthreads();

    if (t < FOUT) {
        const float* W3s = W3 + (size_t)s * 256 * FOUT;
        float a3 = b3[s * FOUT + t];
        for (int i = 0; i < 256; i++) a3 += W3s[i * FOUT + t] * h2[i];
        o[t] = a3;
    }
    __syncthreads();

    if (t == 0) {
        const float* sw = start_w + s * 21;
        const float* ew = end_w + s * 21;
        // start offset
        float m = -1e30f;
        for (int j = 0; j < 21; j++) m = fmaxf(m, o[j]);
        float den = 0.f, num = 0.f;
        for (int j = 0; j < 21; j++) { float e = __expf(o[j] - m); den += e; num += e * sw[j]; }
        float so = num / den;
        // end offset
        m = -1e30f;
        for (int j = 0; j < 21; j++) m = fmaxf(m, o[21 + j]);
        den = 0.f; num = 0.f;
        for (int j = 0; j < 21; j++) { float e = __expf(o[21 + j] - m); den += e; num += e * ew[j]; }
        float eo = num / den;

        float stt = anchors[a * 2], enn = anchors[a * 2 + 1];
        out[a * 2]     = fminf(fmaxf(stt + so, 0.f), al);
        out[a * 2 + 1] = fminf(fmaxf(enn + eo, 0.f), al);
        out[2 * NA + a] = o[42];                      // conf
    }
    if (t < 4) out[3 * NA + a * 4 + t] = o[43 + t];   // cls
}

// ---------------- launcher ----------------
extern "C" void kernel_launch(void* const* d_in, const int* in_sizes, int n_in,
                              void* d_out, int out_size)
{
    const float* emb   = (const float*)d_in[0];   // node_embeddings [512,128]
    const float* tp    = (const float*)d_in[1];   // time_positions [512,1]
    const float* pred  = (const float*)d_in[2];   // node_pred [512,5]
    const float* al_p  = (const float*)d_in[3];   // audio_len scalar
    const float* anc   = (const float*)d_in[4];   // cur_anchor_intervals [192,2]
    const float* kern  = (const float*)d_in[5];   // smooth_kernel [5]
    const float* fWih  = (const float*)d_in[6];   // [3,2,384,128]
    const float* fWhh  = (const float*)d_in[7];   // [3,2,384,128]
    const float* fbih  = (const float*)d_in[8];   // [3,2,384]
    const float* fbhh  = (const float*)d_in[9];   // [3,2,384]
    const float* aWih  = (const float*)d_in[10];  // [3,2,3,1]
    const float* aWhh  = (const float*)d_in[11];  // [3,2,3,1]
    const float* abih  = (const float*)d_in[12];  // [3,2,3]
    const float* abhh  = (const float*)d_in[13];  // [3,2,3]
    const float* sw    = (const float*)d_in[14];  // start_w [3,21]
    const float* ew    = (const float*)d_in[15];  // end_w [3,21]
    const float* W1    = (const float*)d_in[16];  // [3,259,256]
    const float* b1    = (const float*)d_in[17];
    const float* W2    = (const float*)d_in[18];  // [3,256,256]
    const float* b2    = (const float*)d_in[19];
    const float* W3    = (const float*)d_in[20];  // [3,256,47]
    const float* b3    = (const float*)d_in[21];
    float* outp = (float*)d_out;

    k_pre<<<(N_NODES * DIM + 255) / 256, 256>>>(emb, tp, pred, al_p, kern);
    k_gi<<<dim3(N_NODES / 16, 6), 384>>>(fWih, fbih);
    k_gru<<<dim3(NA, 2), 384>>>(anc, fWhh, fbhh, aWih, aWhh, abih, abhh);
    k_head<<<NA, 256>>>(anc, al_p, W1, b1, W2, b2, W3, b3, sw, ew, outp);
}

// round 2
// speedup vs baseline: 1.2447x; 1.2447x over previous
#include <cuda_runtime.h>
#include <math.h>

#define N_NODES 512
#define DIM 128
#define NA 192          // total anchors
#define G3 384          // 3*DIM

// ---------------- scratch (no allocations allowed) ----------------
__device__ float g_x[N_NODES * DIM];
__device__ float g_abn[N_NODES];
__device__ float g_tpos[N_NODES];
__device__ float g_Gi[6 * N_NODES * G3];
__device__ float g_hout[NA * 2 * DIM];
__device__ float g_abnout[NA * 2];
__device__ float g_WihT[6 * DIM * G3];   // [sd][k][row]
__device__ float g_WhhT[6 * DIM * G3];   // [sd][k][row]
__device__ int   g_perm[NA];

__device__ __forceinline__ float sigf(float x) { return 1.f / (1.f + __expf(-x)); }
__device__ __forceinline__ float tanhfast(float x) { return 2.f / (1.f + __expf(-2.f * x)) - 1.f; }

// ---------------- kernel 1: preprocess ----------------
__global__ void k_pre(const float* __restrict__ emb, const float* __restrict__ tp,
                      const float* __restrict__ pred, const float* __restrict__ al_p,
                      const float* __restrict__ kern)
{
    int tid = blockIdx.x * blockDim.x + threadIdx.x;
    if (tid < N_NODES * DIM) {
        int n = tid >> 7, d = tid & 127;
        float freq = (10.f / 127.f) * (float)d;
        g_x[tid] = emb[tid] + 0.05f * sinf(tp[n] * freq);
    }
    if (tid < N_NODES) {
        int n = tid;
        float kv[5];
        #pragma unroll
        for (int k = 0; k < 5; k++) kv[k] = kern[k];
        float sv[5];
        #pragma unroll
        for (int c = 0; c < 5; c++) {
            float acc = 0.f;
            #pragma unroll
            for (int k = 0; k < 5; k++) {
                int nn = n + k - 2;
                if (nn >= 0 && nn < N_NODES) acc += kv[k] * pred[nn * 5 + c];
            }
            sv[c] = acc;
        }
        float m = sv[0];
        #pragma unroll
        for (int c = 1; c < 5; c++) m = fmaxf(m, sv[c]);
        float den = 0.f;
        #pragma unroll
        for (int c = 0; c < 5; c++) den += __expf(sv[c] - m);
        g_abn[n] = __expf(sv[0] - m) / den;
        g_tpos[n] = tp[n] * al_p[0];
    }
}

// ---------------- kernel 1b: transpose GRU weights for coalesced loads ----------------
__global__ void k_tr(const float* __restrict__ Wih, const float* __restrict__ Whh)
{
    int o = blockIdx.x * 256 + threadIdx.x;
    const int total = 6 * DIM * G3;
    if (o >= total) return;
    int sd = o / (DIM * G3);
    int r  = o % (DIM * G3);
    int k  = r / G3;
    int row = r % G3;
    size_t src = (size_t)sd * G3 * DIM + (size_t)row * DIM + k;
    g_WihT[o] = Wih[src];
    g_WhhT[o] = Whh[src];
}

// ---------------- kernel 1c: rank anchors by width (desc) for wave balance ----------------
__global__ void k_rank(const float* __restrict__ anchors)
{
    int i = threadIdx.x;
    if (i >= NA) return;
    float w = anchors[2 * i + 1] - anchors[2 * i];
    int r = 0;
    for (int j = 0; j < NA; j++) {
        float wj = anchors[2 * j + 1] - anchors[2 * j];
        if (wj > w || (wj == w && j < i)) r++;
    }
    g_perm[r] = i;
}

// ---------------- kernel 2: Gi = x @ Wih^T + bih, f32x2 over node pairs ----------------
__global__ __launch_bounds__(384) void k_gi(const float* __restrict__ bih)
{
    int sd = blockIdx.y;
    int tile = blockIdx.x;      // 16 nodes per tile
    int t = threadIdx.x;
    __shared__ __align__(16) float sxT[DIM][20];   // pad 20: 16B-aligned rows, spread banks
    for (int i = t; i < DIM * 16; i += 384) {
        int k = i >> 4, nn = i & 15;
        sxT[k][nn] = g_x[(tile * 16 + nn) * DIM + k];
    }
    __syncthreads();

    unsigned hb;
    asm("{.reg .u64 t0; cvta.to.shared.u64 t0,%1; cvt.u32.u64 %0,t0;}" : "=r"(hb) : "l"(&sxT[0][0]));

    const float* wt = g_WihT + (size_t)sd * DIM * G3 + t;
    unsigned long long acc[8];
    #pragma unroll
    for (int j = 0; j < 8; j++) acc[j] = 0ull;

    for (int k = 0; k < DIM; k++) {
        float wk = wt[(size_t)k * G3];
        unsigned long long w2;
        asm("mov.b64 %0,{%1,%1};" : "=l"(w2) : "f"(wk));
        unsigned rowaddr = hb + k * 80;
        #pragma unroll
        for (int q = 0; q < 4; q++) {
            unsigned long long h0, h1;
            asm volatile("ld.shared.v2.b64 {%0,%1},[%2];" : "=l"(h0), "=l"(h1) : "r"(rowaddr + q * 16));
            asm("fma.rn.f32x2 %0,%1,%2,%0;" : "+l"(acc[2 * q])     : "l"(w2), "l"(h0));
            asm("fma.rn.f32x2 %0,%1,%2,%0;" : "+l"(acc[2 * q + 1]) : "l"(w2), "l"(h1));
        }
    }
    float b = bih[sd * G3 + t];
    #pragma unroll
    for (int j = 0; j < 8; j++) {
        float lo, hi;
        asm("mov.b64 {%0,%1},%2;" : "=f"(lo), "=f"(hi) : "l"(acc[j]));
        g_Gi[((size_t)sd * N_NODES + tile * 16 + 2 * j)     * G3 + t] = lo + b;
        g_Gi[((size_t)sd * N_NODES + tile * 16 + 2 * j + 1) * G3 + t] = hi + b;
    }
}

// ---------------- kernel 3: per-(anchor,dir) GRU recurrence (f32x2 dot) ----------------
__global__ __launch_bounds__(384, 1) void k_gru(const float* __restrict__ anchors,
                                                const float* __restrict__ bhh,
                                                const float* __restrict__ aWih,
                                                const float* __restrict__ aWhh,
                                                const float* __restrict__ abih,
                                                const float* __restrict__ abhh)
{
    int dir = blockIdx.y;
    int t = threadIdx.x;

    __shared__ int sh_a;
    __shared__ __align__(16) float sh_h[DIM];
    __shared__ float sh_gh[G3];
    __shared__ unsigned short sh_idx[N_NODES];
    __shared__ int sh_len;
    __shared__ float sh_abn_h;
    __shared__ float sh_aw[12];

    if (t == 0) sh_a = g_perm[blockIdx.x];
    __syncthreads();
    int a = sh_a;
    int s = a >> 6;
    int sd = s * 2 + dir;

    float stt = anchors[a * 2], enn = anchors[a * 2 + 1];

    // compact selected nodes (original order) with warp 0
    if (t < 32) {
        int off = 0;
        for (int base = 0; base < N_NODES; base += 32) {
            int n = base + t;
            float tp = g_tpos[n];
            bool m = (tp >= stt) && (tp <= enn);
            unsigned bal = __ballot_sync(0xffffffffu, m);
            if (m) sh_idx[off + __popc(bal & ((1u << t) - 1u))] = (unsigned short)n;
            off += __popc(bal);
        }
        if (t == 0) { sh_len = off; sh_abn_h = 0.f; }
    }
    if (t < DIM) sh_h[t] = 0.f;
    if (t >= 32 && t < 35) {
        int j = t - 32, base = sd * 3;
        sh_aw[j]     = aWih[base + j];
        sh_aw[3 + j] = aWhh[base + j];
        sh_aw[6 + j] = abih[base + j];
        sh_aw[9 + j] = abhh[base + j];
    }

    // recurrent weights into registers, packed f32x2 over k pairs (coalesced loads)
    const float* wt = g_WhhT + (size_t)sd * DIM * G3 + t;
    unsigned long long w[64];
    #pragma unroll
    for (int k = 0; k < 64; k++) {
        float w0 = wt[(size_t)(2 * k) * G3];
        float w1 = wt[(size_t)(2 * k + 1) * G3];
        asm("mov.b64 %0,{%1,%2};" : "=l"(w[k]) : "f"(w0), "f"(w1));
    }
    float bh = bhh[sd * G3 + t];

    unsigned hb;
    asm("{.reg .u64 t0; cvta.to.shared.u64 t0,%1; cvt.u32.u64 %0,t0;}" : "=r"(hb) : "l"((float*)sh_h));
    __syncthreads();

    int len = sh_len;
    const float* Gi = g_Gi + (size_t)sd * N_NODES * G3;

    for (int step = 0; step < len; step++) {
        int node = dir ? (int)sh_idx[len - 1 - step] : (int)sh_idx[step];
        float gi_r = 0, gi_z = 0, gi_n = 0, ab_in = 0;
        if (t < DIM) {
            const float* gp = Gi + (size_t)node * G3;
            gi_r = gp[t]; gi_z = gp[DIM + t]; gi_n = gp[2 * DIM + t];
        }
        if (t == 128) ab_in = g_abn[node];

        // gh[t] = Whh[t]·h + bhh[t], 4 f32x2 accumulator chains
        unsigned long long a0 = 0, a1 = 0, a2 = 0, a3 = 0;
        #pragma unroll
        for (int i = 0; i < 16; i++) {
            unsigned long long h0, h1, h2, h3;
            asm volatile("ld.shared.v2.b64 {%0,%1},[%2];" : "=l"(h0), "=l"(h1) : "r"(hb + i * 32));
            asm volatile("ld.shared.v2.b64 {%0,%1},[%2];" : "=l"(h2), "=l"(h3) : "r"(hb + i * 32 + 16));
            asm("fma.rn.f32x2 %0,%1,%2,%0;" : "+l"(a0) : "l"(w[4 * i])     , "l"(h0));
            asm("fma.rn.f32x2 %0,%1,%2,%0;" : "+l"(a1) : "l"(w[4 * i + 1]) , "l"(h1));
            asm("fma.rn.f32x2 %0,%1,%2,%0;" : "+l"(a2) : "l"(w[4 * i + 2]) , "l"(h2));
            asm("fma.rn.f32x2 %0,%1,%2,%0;" : "+l"(a3) : "l"(w[4 * i + 3]) , "l"(h3));
        }
        float p0, p1, p2, p3, p4, p5, p6, p7;
        asm("mov.b64 {%0,%1},%2;" : "=f"(p0), "=f"(p1) : "l"(a0));
        asm("mov.b64 {%0,%1},%2;" : "=f"(p2), "=f"(p3) : "l"(a1));
        asm("mov.b64 {%0,%1},%2;" : "=f"(p4), "=f"(p5) : "l"(a2));
        asm("mov.b64 {%0,%1},%2;" : "=f"(p6), "=f"(p7) : "l"(a3));
        sh_gh[t] = bh + (((p0 + p1) + (p2 + p3)) + ((p4 + p5) + (p6 + p7)));
        __syncthreads();

        if (t < DIM) {
            float r  = sigf(gi_r + sh_gh[t]);
            float z  = sigf(gi_z + sh_gh[DIM + t]);
            float nn = tanhfast(gi_n + r * sh_gh[2 * DIM + t]);
            sh_h[t] = (1.f - z) * nn + z * sh_h[t];
        } else if (t == 128) {
            float h = sh_abn_h;
            float r  = sigf(sh_aw[0] * ab_in + sh_aw[6] + sh_aw[3] * h + sh_aw[9]);
            float z  = sigf(sh_aw[1] * ab_in + sh_aw[7] + sh_aw[4] * h + sh_aw[10]);
            float nn = tanhfast(sh_aw[2] * ab_in + sh_aw[8] + r * (sh_aw[5] * h + sh_aw[11]));
            sh_abn_h = (1.f - z) * nn + z * h;
        }
        __syncthreads();
    }

    if (t < DIM) g_hout[((size_t)a * 2 + dir) * DIM + t] = sh_h[t];
    if (t == 128) g_abnout[a * 2 + dir] = sh_abn_h;
}

// ---------------- kernel 4: per-anchor MLP head, 8-way ILP ----------------
__global__ __launch_bounds__(256) void k_head(const float* __restrict__ anchors,
                                              const float* __restrict__ al_p,
                                              const float* __restrict__ W1, const float* __restrict__ b1,
                                              const float* __restrict__ W2, const float* __restrict__ b2,
                                              const float* __restrict__ W3, const float* __restrict__ b3,
                                              const float* __restrict__ start_w,
                                              const float* __restrict__ end_w,
                                              float* __restrict__ out)
{
    int a = blockIdx.x;
    int s = a >> 6;
    int t = threadIdx.x;
    const int FIN = 2 * DIM + 3;   // 259
    const int FOUT = 47;

    __shared__ float sf[FIN + 1];
    __shared__ float h1[256];
    __shared__ float h2[256];
    __shared__ float o[FOUT];
    __shared__ float soeo[2];

    float al = al_p[0];
    if (t < DIM) {
        sf[t]       = g_hout[((size_t)a * 2 + 0) * DIM + t];
        sf[DIM + t] = g_hout[((size_t)a * 2 + 1) * DIM + t];
    }
    if (t == 0) {
        sf[256] = 0.5f * (g_abnout[a * 2] + g_abnout[a * 2 + 1]);
        float stt = anchors[a * 2], enn = anchors[a * 2 + 1];
        sf[257] = (stt + enn) * 0.5f / al;
        sf[258] = (enn - stt) / al;
    }
    __syncthreads();

    // layer 1
    {
        const float* W = W1 + (size_t)s * FIN * 256 + t;
        float acc[8];
        #pragma unroll
        for (int j = 0; j < 8; j++) acc[j] = 0.f;
        for (int i = 0; i < 256; i += 8) {
            #pragma unroll
            for (int j = 0; j < 8; j++) acc[j] += W[(size_t)(i + j) * 256] * sf[i + j];
        }
        acc[0] += W[(size_t)256 * 256] * sf[256];
        acc[1] += W[(size_t)257 * 256] * sf[257];
        acc[2] += W[(size_t)258 * 256] * sf[258];
        float r = (((acc[0] + acc[1]) + (acc[2] + acc[3])) + ((acc[4] + acc[5]) + (acc[6] + acc[7])))
                  + b1[s * 256 + t];
        h1[t] = fmaxf(r, 0.f);
    }
    __syncthreads();

    // layer 2
    {
        const float* W = W2 + (size_t)s * 256 * 256 + t;
        float acc[8];
        #pragma unroll
        for (int j = 0; j < 8; j++) acc[j] = 0.f;
        for (int i = 0; i < 256; i += 8) {
            #pragma unroll
            for (int j = 0; j < 8; j++) acc[j] += W[(size_t)(i + j) * 256] * h1[i + j];
        }
        float r = (((acc[0] + acc[1]) + (acc[2] + acc[3])) + ((acc[4] + acc[5]) + (acc[6] + acc[7])))
                  + b2[s * 256 + t];
        h2[t] = fmaxf(r, 0.f);
    }
    __syncthreads();

    // layer 3 (47 outputs)
    if (t < FOUT) {
        const float* W = W3 + (size_t)s * 256 * FOUT + t;
        float acc[8];
        #pragma unroll
        for (int j = 0; j < 8; j++) acc[j] = 0.f;
        for (int i = 0; i < 256; i += 8) {
            #pragma unroll
            for (int j = 0; j < 8; j++) acc[j] += W[(size_t)(i + j) * FOUT] * h2[i + j];
        }
        o[t] = (((acc[0] + acc[1]) + (acc[2] + acc[3])) + ((acc[4] + acc[5]) + (acc[6] + acc[7])))
               + b3[s * FOUT + t];
    }
    __syncthreads();

    if (t < 2) {
        const float* wv = (t == 0) ? (start_w + s * 21) : (end_w + s * 21);
        const float* ov = o + t * 21;
        float m = -1e30f;
        for (int j = 0; j < 21; j++) m = fmaxf(m, ov[j]);
        float den = 0.f, num = 0.f;
        for (int j = 0; j < 21; j++) { float e = __expf(ov[j] - m); den += e; num += e * wv[j]; }
        soeo[t] = num / den;
    }
    __syncthreads();

    if (t == 0) {
        float stt = anchors[a * 2], enn = anchors[a * 2 + 1];
        out[a * 2]      = fminf(fmaxf(stt + soeo[0], 0.f), al);
        out[a * 2 + 1]  = fminf(fmaxf(enn + soeo[1], 0.f), al);
        out[2 * NA + a] = o[42];
    }
    if (t < 4) out[3 * NA + a * 4 + t] = o[43 + t];
}

// ---------------- launcher ----------------
extern "C" void kernel_launch(void* const* d_in, const int* in_sizes, int n_in,
                              void* d_out, int out_size)
{
    const float* emb   = (const float*)d_in[0];
    const float* tp    = (const float*)d_in[1];
    const float* pred  = (const float*)d_in[2];
    const float* al_p  = (const float*)d_in[3];
    const float* anc   = (const float*)d_in[4];
    const float* kern  = (const float*)d_in[5];
    const float* fWih  = (const float*)d_in[6];
    const float* fWhh  = (const float*)d_in[7];
    const float* fbih  = (const float*)d_in[8];
    const float* fbhh  = (const float*)d_in[9];
    const float* aWih  = (const float*)d_in[10];
    const float* aWhh  = (const float*)d_in[11];
    const float* abih  = (const float*)d_in[12];
    const float* abhh  = (const float*)d_in[13];
    const float* sw    = (const float*)d_in[14];
    const float* ew    = (const float*)d_in[15];
    const float* W1    = (const float*)d_in[16];
    const float* b1    = (const float*)d_in[17];
    const float* W2    = (const float*)d_in[18];
    const float* b2    = (const float*)d_in[19];
    const float* W3    = (const float*)d_in[20];
    const float* b3    = (const float*)d_in[21];
    float* outp = (float*)d_out;

    k_pre<<<(N_NODES * DIM + 255) / 256, 256>>>(emb, tp, pred, al_p, kern);
    k_tr<<<(6 * DIM * G3 + 255) / 256, 256>>>(fWih, fWhh);
    k_rank<<<1, NA>>>(anc);
    k_gi<<<dim3(N_NODES / 16, 6), 384>>>(fbih);
    k_gru<<<dim3(NA, 2), 384>>>(anc, fbhh, aWih, aWhh, abih, abhh);
    k_head<<<NA, 256>>>(anc, al_p, W1, b1, W2, b2, W3, b3, sw, ew, outp);
}